// round 1
// baseline (speedup 1.0000x reference)
#include <cuda_runtime.h>
#include <cuda_bf16.h>

// Problem constants (fixed by setup_inputs)
#define Bb 4
#define Ts 4096
#define Dd 2560
#define Hh 10
#define BW 256
#define Mrows (Bb*Ts)   // 16384

// Scratch: interleaved (a_eff, x_norm) per element, plus softplus table.
__device__ float2 g_ax[(size_t)Bb * Ts * Dd];   // ~336 MB static device scratch
__device__ float  g_sp[Dd];

// ---------------------------------------------------------------------------
// Kernel 0: softplus(recurrent_param) -> g_sp  (2560 elements, trivial)
// ---------------------------------------------------------------------------
__global__ void sp_kernel(const float* __restrict__ rp) {
    int d = blockIdx.x * blockDim.x + threadIdx.x;
    if (d < Dd) {
        float x = rp[d];
        float s = (x > 20.0f) ? x : log1pf(__expf(x));
        g_sp[d] = s;
    }
}

// ---------------------------------------------------------------------------
// Kernel 1: block-diagonal gates GEMM + fused elementwise epilogue.
// Per head h: C = A(16384 x 256) * [Wig | Wrg](256 x 2*256)
// Block tile: BM=128 rows x BN=64 gate-columns, BOTH gates accumulated in-block
// so the epilogue has (ig_pre, rg_pre) pairs co-located.
// ---------------------------------------------------------------------------
#define BM 128
#define BN 64
#define BK 16

__global__ __launch_bounds__(256, 2) void gates_kernel(
    const float* __restrict__ act, const int* __restrict__ pos,
    const float* __restrict__ wig, const float* __restrict__ big,
    const float* __restrict__ wrg, const float* __restrict__ brg)
{
    __shared__ float As[BK][BM];   // A tile transposed (k-major)  8 KB
    __shared__ float Wi[BK][BN];   // ig weight tile               4 KB
    __shared__ float Wr[BK][BN];   // rg weight tile               4 KB

    const int h  = blockIdx.z;
    const int jb = blockIdx.x * BN;   // gate-column base within head [0,256)
    const int rb = blockIdx.y * BM;   // row base within M=16384

    const int tid = threadIdx.x;
    const int tx  = tid & 15;         // -> 4 gate columns
    const int ty  = tid >> 4;         // -> 8 rows
    const int j0  = tx * 4;
    const int r0  = ty * 8;

    float acc_i[8][4];
    float acc_r[8][4];
    #pragma unroll
    for (int u = 0; u < 8; u++)
        #pragma unroll
        for (int v = 0; v < 4; v++) { acc_i[u][v] = 0.0f; acc_r[u][v] = 0.0f; }

    const float* acth = act + (size_t)h * BW;          // head column offset
    const float* wigh = wig + (size_t)h * BW * BW;
    const float* wrgh = wrg + (size_t)h * BW * BW;

    for (int k0 = 0; k0 < BW; k0 += BK) {
        // Load A tile (128 rows x 16 k) as float4, store transposed.
        #pragma unroll
        for (int l = 0; l < 2; l++) {
            int li = tid + l * 256;
            int r  = li >> 2;               // 0..127
            int kq = (li & 3) * 4;          // 0,4,8,12
            float4 v = *(const float4*)(acth + (size_t)(rb + r) * Dd + k0 + kq);
            As[kq + 0][r] = v.x;
            As[kq + 1][r] = v.y;
            As[kq + 2][r] = v.z;
            As[kq + 3][r] = v.w;
        }
        // Load W tiles (16 x 64 each gate), one float4 per thread per gate.
        {
            int kr = tid >> 4;              // 0..15
            int cq = (tid & 15) * 4;        // 0..60
            *(float4*)&Wi[kr][cq] = *(const float4*)(wigh + (size_t)(k0 + kr) * BW + jb + cq);
            *(float4*)&Wr[kr][cq] = *(const float4*)(wrgh + (size_t)(k0 + kr) * BW + jb + cq);
        }
        __syncthreads();

        #pragma unroll
        for (int k = 0; k < BK; k++) {
            float4 a0 = *(float4*)&As[k][r0];
            float4 a1 = *(float4*)&As[k][r0 + 4];
            float4 wi = *(float4*)&Wi[k][j0];
            float4 wr = *(float4*)&Wr[k][j0];
            float av[8]  = {a0.x, a0.y, a0.z, a0.w, a1.x, a1.y, a1.z, a1.w};
            float wiv[4] = {wi.x, wi.y, wi.z, wi.w};
            float wrv[4] = {wr.x, wr.y, wr.z, wr.w};
            #pragma unroll
            for (int u = 0; u < 8; u++) {
                #pragma unroll
                for (int v = 0; v < 4; v++) {
                    acc_i[u][v] = fmaf(av[u], wiv[v], acc_i[u][v]);
                    acc_r[u][v] = fmaf(av[u], wrv[v], acc_r[u][v]);
                }
            }
        }
        __syncthreads();
    }

    // -------- fused epilogue --------
    float bi[4], br[4], sp4[4];
    #pragma unroll
    for (int v = 0; v < 4; v++) {
        int dg = h * BW + jb + j0 + v;
        bi[v]  = big[h * BW + jb + j0 + v];
        br[v]  = brg[h * BW + jb + j0 + v];
        sp4[v] = g_sp[dg];
    }

    #pragma unroll
    for (int u = 0; u < 8; u++) {
        int R = rb + r0 + u;                 // flattened (b,t) row
        bool reset = (pos[R] == 0);          // position_ids[b,t] == 0
        size_t base = (size_t)R * Dd + h * BW + jb + j0;
        float4 av = *(const float4*)(act + base);
        float actv[4] = {av.x, av.y, av.z, av.w};
        float2 outv[4];
        #pragma unroll
        for (int v = 0; v < 4; v++) {
            float ig = 1.0f / (1.0f + __expf(-(acc_i[u][v] + bi[v])));
            float rg = 1.0f / (1.0f + __expf(-(acc_r[u][v] + br[v])));
            float log_a = -8.0f * rg * sp4[v];
            float a = __expf(log_a);
            // 1 - a^2 with one rounding; a < 1 strictly, clamp for safety
            float m = sqrtf(fmaxf(fmaf(-a, a, 1.0f), 0.0f));
            float aeff = reset ? 0.0f : a;
            float mult = reset ? 1.0f : m;
            outv[v].x = aeff;
            outv[v].y = actv[v] * ig * mult;
        }
        float4* op = (float4*)&g_ax[base];
        op[0] = make_float4(outv[0].x, outv[0].y, outv[1].x, outv[1].y);
        op[1] = make_float4(outv[2].x, outv[2].y, outv[3].x, outv[3].y);
    }
}

// ---------------------------------------------------------------------------
// Kernel 2: linear recurrence scan. One thread owns one (b,d) channel for the
// full T. Loads are float2 (a,x) batched UNR at a time for MLP; the FMA chain
// is the only serial dependency (4 cyc * 4096).
// ---------------------------------------------------------------------------
#define SCAN_THREADS 128
#define UNR 16

__global__ __launch_bounds__(SCAN_THREADS) void scan_kernel(float* __restrict__ out) {
    int ch = blockIdx.x * SCAN_THREADS + threadIdx.x;   // 0..B*D-1
    int b  = ch / Dd;
    int d  = ch - b * Dd;
    size_t idx = (size_t)b * Ts * Dd + d;

    float h = 0.0f;
    for (int t = 0; t < Ts; t += UNR) {
        float2 v[UNR];
        #pragma unroll
        for (int u = 0; u < UNR; u++)
            v[u] = g_ax[idx + (size_t)(t + u) * Dd];
        #pragma unroll
        for (int u = 0; u < UNR; u++) {
            h = fmaf(v[u].x, h, v[u].y);
            out[idx + (size_t)(t + u) * Dd] = h;
        }
    }
}

// ---------------------------------------------------------------------------
extern "C" void kernel_launch(void* const* d_in, const int* in_sizes, int n_in,
                              void* d_out, int out_size) {
    const float* act = (const float*)d_in[0];
    const int*   pos = (const int*)  d_in[1];
    const float* wig = (const float*)d_in[2];
    const float* big = (const float*)d_in[3];
    const float* wrg = (const float*)d_in[4];
    const float* brg = (const float*)d_in[5];
    const float* rp  = (const float*)d_in[6];
    float* out = (float*)d_out;

    sp_kernel<<<(Dd + 255) / 256, 256>>>(rp);

    dim3 grid(BW / BN, Mrows / BM, Hh);   // (4, 128, 10) = 5120 blocks
    gates_kernel<<<grid, 256>>>(act, pos, wig, big, wrg, brg);

    scan_kernel<<<(Bb * Dd) / SCAN_THREADS, SCAN_THREADS>>>(out);
}

// round 3
// speedup vs baseline: 1.3910x; 1.3910x over previous
#include <cuda_runtime.h>
#include <cuda_bf16.h>
#include <cstdint>

// Problem constants (fixed by setup_inputs)
#define Bb 4
#define Ts 4096
#define Dd 2560
#define Hh 10
#define BW 256
#define Mrows (Bb*Ts)   // 16384

// Scratch
__device__ float2 g_ax[(size_t)Bb * Ts * Dd];    // interleaved (a_eff, x_norm)
__device__ float  g_sp[Dd];                      // softplus(recurrent_param)
// Interleaved, K-major transposed weights: g_wT[h][n=2j+gate][k]
__device__ float  g_wT[(size_t)Hh * 512 * BW];

// ---------------------------------------------------------------------------
__device__ __forceinline__ uint32_t f2tf32(float x) {
    uint32_t u; asm("cvt.rna.tf32.f32 %0, %1;" : "=r"(u) : "f"(x)); return u;
}
__device__ __forceinline__ void mma_tf32(float* c, const uint32_t* a, const uint32_t* b) {
    asm volatile("mma.sync.aligned.m16n8k8.row.col.f32.tf32.tf32.f32 "
                 "{%0,%1,%2,%3}, {%4,%5,%6,%7}, {%8,%9}, {%0,%1,%2,%3};"
                 : "+f"(c[0]), "+f"(c[1]), "+f"(c[2]), "+f"(c[3])
                 : "r"(a[0]), "r"(a[1]), "r"(a[2]), "r"(a[3]), "r"(b[0]), "r"(b[1]));
}

// ---------------------------------------------------------------------------
// Kernel 0: softplus table
// ---------------------------------------------------------------------------
__global__ void sp_kernel(const float* __restrict__ rp) {
    int d = blockIdx.x * blockDim.x + threadIdx.x;
    if (d < Dd) {
        float x = rp[d];
        g_sp[d] = (x > 20.0f) ? x : log1pf(__expf(x));
    }
}

// ---------------------------------------------------------------------------
// Kernel 0b: weight transpose+interleave: g_wT[h][2j+gate][k] = w_gate[h][k][j]
// ---------------------------------------------------------------------------
__global__ void wt_kernel(const float* __restrict__ wig, const float* __restrict__ wrg) {
    int idx = blockIdx.x * blockDim.x + threadIdx.x;   // Hh*512*256 total
    int k = idx & (BW - 1);
    int n = (idx >> 8) & 511;
    int h = idx >> 17;
    int j = n >> 1;
    const float* src = (n & 1) ? wrg : wig;
    g_wT[idx] = src[(size_t)h * BW * BW + (size_t)k * BW + j];
}

// ---------------------------------------------------------------------------
// Kernel 1: tf32 mma.sync gates GEMM + fused epilogue.
// CTA tile: 128 rows x 256 interleaved-cols (=128 j's), K=256 in 8 stages of 32.
// 8 warps in 2(M) x 4(N); warp tile 64x64.
// smem pitch 36 floats/row: coalesced stores AND conflict-free frag loads.
// ---------------------------------------------------------------------------
#define PITCH 36
#define A_FL (128 * PITCH)    // 4608 floats per A stage
#define W_FL (256 * PITCH)    // 9216 floats per W stage
#define SMEM_FL (2 * A_FL + 2 * W_FL)   // 27648 floats = 110592 B

__global__ __launch_bounds__(256, 1) void gates_mma_kernel(
    const float* __restrict__ act, const int* __restrict__ pos,
    const float* __restrict__ big, const float* __restrict__ brg)
{
    extern __shared__ float sm[];
    float* const A0 = sm;
    float* const A1 = sm + A_FL;
    float* const W0 = sm + 2 * A_FL;
    float* const W1 = sm + 2 * A_FL + W_FL;

    const int tid = threadIdx.x;
    const int wid = tid >> 5, lane = tid & 31;
    const int g = lane >> 2, t = lane & 3;
    const int wm = wid & 1;        // 0..1 -> 64-row slab
    const int wn = wid >> 1;       // 0..3 -> 64-col slab
    const int h  = blockIdx.z;
    const int ny = blockIdx.y;     // N-half (0/1): j base ny*128
    const int rb = blockIdx.x * 128;

    const int sq = tid & 7;        // staging quad (16B)
    const int sr = tid >> 3;       // staging row (32 per pass)

    const float* aG = act  + (size_t)h * BW;                          // [M][2560] col offset
    const float* wG = g_wT + ((size_t)h * 512 + ny * 256) * BW;      // [256][256]

    float acc[4][8][4];
    #pragma unroll
    for (int mt = 0; mt < 4; mt++)
        #pragma unroll
        for (int nt = 0; nt < 8; nt++)
            #pragma unroll
            for (int c = 0; c < 4; c++) acc[mt][nt][c] = 0.0f;

    // ---- stage 0 direct ----
    {
        #pragma unroll
        for (int p = 0; p < 4; p++) {
            int r = sr + p * 32;
            float4 v = *(const float4*)(aG + (size_t)(rb + r) * Dd + sq * 4);
            A0[r * PITCH + sq * 4 + 0] = __uint_as_float(f2tf32(v.x));
            A0[r * PITCH + sq * 4 + 1] = __uint_as_float(f2tf32(v.y));
            A0[r * PITCH + sq * 4 + 2] = __uint_as_float(f2tf32(v.z));
            A0[r * PITCH + sq * 4 + 3] = __uint_as_float(f2tf32(v.w));
        }
        #pragma unroll
        for (int p = 0; p < 8; p++) {
            int r = sr + p * 32;
            float4 v = *(const float4*)(wG + (size_t)r * BW + sq * 4);
            W0[r * PITCH + sq * 4 + 0] = __uint_as_float(f2tf32(v.x));
            W0[r * PITCH + sq * 4 + 1] = __uint_as_float(f2tf32(v.y));
            W0[r * PITCH + sq * 4 + 2] = __uint_as_float(f2tf32(v.z));
            W0[r * PITCH + sq * 4 + 3] = __uint_as_float(f2tf32(v.w));
        }
    }
    __syncthreads();

    #pragma unroll 1
    for (int kt = 0; kt < 8; kt++) {
        const float* Ab = (kt & 1) ? A1 : A0;
        const float* Wb = (kt & 1) ? W1 : W0;
        float* An = (kt & 1) ? A0 : A1;
        float* Wn = (kt & 1) ? W0 : W1;

        // prefetch next stage into regs
        float4 pa[4], pw[8];
        if (kt < 7) {
            int k0 = (kt + 1) * 32;
            #pragma unroll
            for (int p = 0; p < 4; p++)
                pa[p] = *(const float4*)(aG + (size_t)(rb + sr + p * 32) * Dd + k0 + sq * 4);
            #pragma unroll
            for (int p = 0; p < 8; p++)
                pw[p] = *(const float4*)(wG + (size_t)(sr + p * 32) * BW + k0 + sq * 4);
        }

        // compute 4 x k8 steps
        #pragma unroll
        for (int k8 = 0; k8 < 4; k8++) {
            const int kk = k8 * 8 + t;
            uint32_t bf[8][2];
            #pragma unroll
            for (int nt = 0; nt < 8; nt++) {
                int n = wn * 64 + nt * 8 + g;
                bf[nt][0] = __float_as_uint(Wb[n * PITCH + kk]);
                bf[nt][1] = __float_as_uint(Wb[n * PITCH + kk + 4]);
            }
            #pragma unroll
            for (int mt = 0; mt < 4; mt++) {
                int m = wm * 64 + mt * 16 + g;
                uint32_t af[4];
                af[0] = __float_as_uint(Ab[m * PITCH + kk]);
                af[1] = __float_as_uint(Ab[(m + 8) * PITCH + kk]);
                af[2] = __float_as_uint(Ab[m * PITCH + kk + 4]);
                af[3] = __float_as_uint(Ab[(m + 8) * PITCH + kk + 4]);
                #pragma unroll
                for (int nt = 0; nt < 8; nt++)
                    mma_tf32(acc[mt][nt], af, bf[nt]);
            }
        }

        if (kt < 7) {
            #pragma unroll
            for (int p = 0; p < 4; p++) {
                int r = sr + p * 32;
                An[r * PITCH + sq * 4 + 0] = __uint_as_float(f2tf32(pa[p].x));
                An[r * PITCH + sq * 4 + 1] = __uint_as_float(f2tf32(pa[p].y));
                An[r * PITCH + sq * 4 + 2] = __uint_as_float(f2tf32(pa[p].z));
                An[r * PITCH + sq * 4 + 3] = __uint_as_float(f2tf32(pa[p].w));
            }
            #pragma unroll
            for (int p = 0; p < 8; p++) {
                int r = sr + p * 32;
                Wn[r * PITCH + sq * 4 + 0] = __uint_as_float(f2tf32(pw[p].x));
                Wn[r * PITCH + sq * 4 + 1] = __uint_as_float(f2tf32(pw[p].y));
                Wn[r * PITCH + sq * 4 + 2] = __uint_as_float(f2tf32(pw[p].z));
                Wn[r * PITCH + sq * 4 + 3] = __uint_as_float(f2tf32(pw[p].w));
            }
            __syncthreads();
        }
    }

    // -------- fused epilogue --------
    // thread's j for nt: j = ny*128 + wn*32 + nt*4 + t ; gates are (c0,c1)/(c2,c3)
    float bi[8], br[8], sp8[8];
    int dg0 = h * BW + ny * 128 + wn * 32 + t;
    #pragma unroll
    for (int nt = 0; nt < 8; nt++) {
        int dg = dg0 + nt * 4;
        bi[nt]  = big[dg];
        br[nt]  = brg[dg];
        sp8[nt] = g_sp[dg];
    }

    #pragma unroll
    for (int mt = 0; mt < 4; mt++) {
        int r1 = rb + wm * 64 + mt * 16 + g;
        int r2 = r1 + 8;
        bool rs1 = (pos[r1] == 0);
        bool rs2 = (pos[r2] == 0);
        const float* a1p = act + (size_t)r1 * Dd;
        const float* a2p = act + (size_t)r2 * Dd;
        float2* o1 = g_ax + (size_t)r1 * Dd;
        float2* o2 = g_ax + (size_t)r2 * Dd;
        #pragma unroll
        for (int nt = 0; nt < 8; nt++) {
            int dg = dg0 + nt * 4;
            // row r1 : (c0,c1)
            {
                float ig = 1.0f / (1.0f + __expf(-(acc[mt][nt][0] + bi[nt])));
                float rg = 1.0f / (1.0f + __expf(-(acc[mt][nt][1] + br[nt])));
                float a  = __expf(-8.0f * rg * sp8[nt]);
                float m  = sqrtf(fmaxf(fmaf(-a, a, 1.0f), 0.0f));
                float xn = a1p[dg] * ig * (rs1 ? 1.0f : m);
                o1[dg] = make_float2(rs1 ? 0.0f : a, xn);
            }
            // row r2 : (c2,c3)
            {
                float ig = 1.0f / (1.0f + __expf(-(acc[mt][nt][2] + bi[nt])));
                float rg = 1.0f / (1.0f + __expf(-(acc[mt][nt][3] + br[nt])));
                float a  = __expf(-8.0f * rg * sp8[nt]);
                float m  = sqrtf(fmaxf(fmaf(-a, a, 1.0f), 0.0f));
                float xn = a2p[dg] * ig * (rs2 ? 1.0f : m);
                o2[dg] = make_float2(rs2 ? 0.0f : a, xn);
            }
        }
    }
}

// ---------------------------------------------------------------------------
// Kernel 2: linear recurrence scan (memory-bound). 64 thr x 160 CTAs, UNR=32.
// ---------------------------------------------------------------------------
#define SCAN_THREADS 64
#define UNR 32

__global__ __launch_bounds__(SCAN_THREADS) void scan_kernel(float* __restrict__ out) {
    int ch = blockIdx.x * SCAN_THREADS + threadIdx.x;
    int b  = ch / Dd;
    int d  = ch - b * Dd;
    size_t idx = (size_t)b * Ts * Dd + d;

    float hacc = 0.0f;
    #pragma unroll 1
    for (int tt = 0; tt < Ts; tt += UNR) {
        float2 v[UNR];
        #pragma unroll
        for (int u = 0; u < UNR; u++)
            v[u] = g_ax[idx + (size_t)(tt + u) * Dd];
        #pragma unroll
        for (int u = 0; u < UNR; u++) {
            hacc = fmaf(v[u].x, hacc, v[u].y);
            out[idx + (size_t)(tt + u) * Dd] = hacc;
        }
    }
}

// ---------------------------------------------------------------------------
extern "C" void kernel_launch(void* const* d_in, const int* in_sizes, int n_in,
                              void* d_out, int out_size) {
    const float* act = (const float*)d_in[0];
    const int*   pos = (const int*)  d_in[1];
    const float* wig = (const float*)d_in[2];
    const float* big = (const float*)d_in[3];
    const float* wrg = (const float*)d_in[4];
    const float* brg = (const float*)d_in[5];
    const float* rp  = (const float*)d_in[6];
    float* out = (float*)d_out;

    static int smem_set = 0;
    if (!smem_set) {
        cudaFuncSetAttribute(gates_mma_kernel,
                             cudaFuncAttributeMaxDynamicSharedMemorySize,
                             SMEM_FL * 4);
        smem_set = 1;
    }

    sp_kernel<<<(Dd + 255) / 256, 256>>>(rp);
    wt_kernel<<<(Hh * 512 * BW) / 256, 256>>>(wig, wrg);

    dim3 grid(Mrows / 128, 2, Hh);   // (128, 2, 10) = 2560 CTAs
    gates_mma_kernel<<<grid, 256, SMEM_FL * 4>>>(act, pos, big, brg);

    scan_kernel<<<(Bb * Dd) / SCAN_THREADS, SCAN_THREADS>>>(out);
}

// round 4
// speedup vs baseline: 1.9086x; 1.3721x over previous
#include <cuda_runtime.h>
#include <cuda_bf16.h>
#include <cstdint>

// Problem constants (fixed by setup_inputs)
#define Bb 4
#define Ts 4096
#define Dd 2560
#define Hh 10
#define BW 256
#define Mrows (Bb*Ts)   // 16384
#define NCHAN (Bb*Dd)   // 10240

// Scratch
__device__ float2 g_ax[(size_t)Bb * Ts * Dd];    // interleaved (a_eff, x_norm)
__device__ float  g_sp[Dd];                      // softplus(recurrent_param)
__device__ float  g_wT[(size_t)Hh * 512 * BW];   // interleaved K-major weights [h][2j+gate][k]

// chunked-scan partials
#define CH 128
#define NCH (Ts / CH)    // 32
__device__ float g_P[NCH * NCHAN];
__device__ float g_h[NCH * NCHAN];
__device__ float g_H[NCH * NCHAN];

// ---------------------------------------------------------------------------
__device__ __forceinline__ uint32_t smem_u32(const void* p) {
    uint32_t a;
    asm("{ .reg .u64 t; cvta.to.shared.u64 t, %1; cvt.u32.u64 %0, t; }" : "=r"(a) : "l"(p));
    return a;
}
__device__ __forceinline__ void mma_tf32(float* c, const uint32_t* a, const uint32_t* b) {
    asm volatile("mma.sync.aligned.m16n8k8.row.col.f32.tf32.tf32.f32 "
                 "{%0,%1,%2,%3}, {%4,%5,%6,%7}, {%8,%9}, {%0,%1,%2,%3};"
                 : "+f"(c[0]), "+f"(c[1]), "+f"(c[2]), "+f"(c[3])
                 : "r"(a[0]), "r"(a[1]), "r"(a[2]), "r"(a[3]), "r"(b[0]), "r"(b[1]));
}
#define CPA(dst, src) asm volatile("cp.async.cg.shared.global [%0], [%1], 16;" \
                                   :: "r"(dst), "l"(src) : "memory")
#define CPC()  asm volatile("cp.async.commit_group;" ::: "memory")
#define CPW(n) asm volatile("cp.async.wait_group %0;" :: "n"(n) : "memory")

// ---------------------------------------------------------------------------
// Kernel 0: softplus table
// ---------------------------------------------------------------------------
__global__ void sp_kernel(const float* __restrict__ rp) {
    int d = blockIdx.x * blockDim.x + threadIdx.x;
    if (d < Dd) {
        float x = rp[d];
        g_sp[d] = (x > 20.0f) ? x : log1pf(__expf(x));
    }
}

// ---------------------------------------------------------------------------
// Kernel 0b: weight transpose+interleave: g_wT[h][2j+gate][k] = w_gate[h][k][j]
// ---------------------------------------------------------------------------
__global__ void wt_kernel(const float* __restrict__ wig, const float* __restrict__ wrg) {
    int idx = blockIdx.x * blockDim.x + threadIdx.x;   // Hh*512*256 total
    int k = idx & (BW - 1);
    int n = (idx >> 8) & 511;
    int h = idx >> 17;
    int j = n >> 1;
    const float* src = (n & 1) ? wrg : wig;
    g_wT[idx] = src[(size_t)h * BW * BW + (size_t)k * BW + j];
}

// ---------------------------------------------------------------------------
// Kernel 1: tf32 mma.sync gates GEMM + fused epilogue, cp.async 3-stage pipe.
// CTA: 128 rows x 256 interleaved-cols (=128 j's), K=256 in 8 tiles of 32.
// 8 warps 2(M) x 4(N); warp tile 64x64. smem pitch 36 floats (conflict-free).
// ---------------------------------------------------------------------------
#define PITCH 36
#define A_FL (128 * PITCH)                 // 4608 floats
#define W_FL (256 * PITCH)                 // 9216 floats
#define STAGE_FL (A_FL + W_FL)             // 13824 floats = 55296 B
#define SMEM_B (3 * STAGE_FL * 4)          // 165888 B

__global__ __launch_bounds__(256, 1) void gates_mma_kernel(
    const float* __restrict__ act, const int* __restrict__ pos,
    const float* __restrict__ big, const float* __restrict__ brg)
{
    extern __shared__ float sm[];
    const uint32_t sbase = smem_u32(sm);

    const int tid = threadIdx.x;
    const int wid = tid >> 5, lane = tid & 31;
    const int g = lane >> 2, t = lane & 3;
    const int wm = wid & 1;        // 64-row slab
    const int wn = wid >> 1;       // 64-col slab
    const int h  = blockIdx.z;
    const int ny = blockIdx.y;     // N-half: j base ny*128
    const int rb = blockIdx.x * 128;

    const int sq = tid & 7;        // 16B chunk in 128B row
    const int sr = tid >> 3;       // 32 rows per pass

    const float* aG = act  + (size_t)h * BW;
    const float* wG = g_wT + ((size_t)h * 512 + ny * 256) * BW;

    float acc[4][8][4];
    #pragma unroll
    for (int mt = 0; mt < 4; mt++)
        #pragma unroll
        for (int nt = 0; nt < 8; nt++)
            #pragma unroll
            for (int c = 0; c < 4; c++) acc[mt][nt][c] = 0.0f;

    // issue one K-stage via cp.async into buffer `buf`
    auto issue = [&](int kt, int buf) {
        const int k0 = kt * 32;
        uint32_t Ad = sbase + buf * (STAGE_FL * 4);
        uint32_t Wd = Ad + A_FL * 4;
        #pragma unroll
        for (int p = 0; p < 4; p++) {
            int r = sr + p * 32;
            CPA(Ad + r * (PITCH * 4) + sq * 16,
                aG + (size_t)(rb + r) * Dd + k0 + sq * 4);
        }
        #pragma unroll
        for (int p = 0; p < 8; p++) {
            int r = sr + p * 32;
            CPA(Wd + r * (PITCH * 4) + sq * 16,
                wG + (size_t)r * BW + k0 + sq * 4);
        }
    };

    issue(0, 0); CPC();
    issue(1, 1); CPC();

    #pragma unroll 1
    for (int kt = 0; kt < 8; kt++) {
        CPW(1);                 // stage kt landed
        __syncthreads();
        const int buf = kt % 3;
        const float* Ab = sm + buf * STAGE_FL;
        const float* Wb = Ab + A_FL;

        #pragma unroll
        for (int k8 = 0; k8 < 4; k8++) {
            const int kk = k8 * 8 + t;
            uint32_t bf[8][2];
            #pragma unroll
            for (int nt = 0; nt < 8; nt++) {
                int n = wn * 64 + nt * 8 + g;
                bf[nt][0] = __float_as_uint(Wb[n * PITCH + kk]);
                bf[nt][1] = __float_as_uint(Wb[n * PITCH + kk + 4]);
            }
            #pragma unroll
            for (int mt = 0; mt < 4; mt++) {
                int m = wm * 64 + mt * 16 + g;
                uint32_t af[4];
                af[0] = __float_as_uint(Ab[m * PITCH + kk]);
                af[1] = __float_as_uint(Ab[(m + 8) * PITCH + kk]);
                af[2] = __float_as_uint(Ab[m * PITCH + kk + 4]);
                af[3] = __float_as_uint(Ab[(m + 8) * PITCH + kk + 4]);
                #pragma unroll
                for (int nt = 0; nt < 8; nt++)
                    mma_tf32(acc[mt][nt], af, bf[nt]);
            }
        }
        if (kt + 2 < 8) issue(kt + 2, (kt + 2) % 3);
        CPC();
    }

    // -------- fused epilogue --------
    float bi[8], br[8], sp8[8];
    const int dg0 = h * BW + ny * 128 + wn * 32 + t;
    #pragma unroll
    for (int nt = 0; nt < 8; nt++) {
        int dg = dg0 + nt * 4;
        bi[nt]  = big[dg];
        br[nt]  = brg[dg];
        sp8[nt] = g_sp[dg];
    }

    #pragma unroll
    for (int mt = 0; mt < 4; mt++) {
        int r1 = rb + wm * 64 + mt * 16 + g;
        int r2 = r1 + 8;
        bool rs1 = (pos[r1] == 0);
        bool rs2 = (pos[r2] == 0);
        const float* a1p = act + (size_t)r1 * Dd;
        const float* a2p = act + (size_t)r2 * Dd;
        float2* o1 = g_ax + (size_t)r1 * Dd;
        float2* o2 = g_ax + (size_t)r2 * Dd;
        #pragma unroll
        for (int nt = 0; nt < 8; nt++) {
            int dg = dg0 + nt * 4;
            {
                float ig = 1.0f / (1.0f + __expf(-(acc[mt][nt][0] + bi[nt])));
                float rg = 1.0f / (1.0f + __expf(-(acc[mt][nt][1] + br[nt])));
                float a  = __expf(-8.0f * rg * sp8[nt]);
                float m  = sqrtf(fmaxf(fmaf(-a, a, 1.0f), 0.0f));
                float xn = a1p[dg] * ig * (rs1 ? 1.0f : m);
                o1[dg] = make_float2(rs1 ? 0.0f : a, xn);
            }
            {
                float ig = 1.0f / (1.0f + __expf(-(acc[mt][nt][2] + bi[nt])));
                float rg = 1.0f / (1.0f + __expf(-(acc[mt][nt][3] + br[nt])));
                float a  = __expf(-8.0f * rg * sp8[nt]);
                float m  = sqrtf(fmaxf(fmaf(-a, a, 1.0f), 0.0f));
                float xn = a2p[dg] * ig * (rs2 ? 1.0f : m);
                o2[dg] = make_float2(rs2 ? 0.0f : a, xn);
            }
        }
    }
}

// ---------------------------------------------------------------------------
// Kernel 2a: per-chunk local scan -> (product, local final state)
// grid (NCHAN/128, NCH), block 128. Coalesced over d.
// ---------------------------------------------------------------------------
__global__ __launch_bounds__(128) void scan_part_kernel() {
    int ch = blockIdx.x * 128 + threadIdx.x;     // 0..NCHAN-1
    int c  = blockIdx.y;
    int b  = ch / Dd;
    int d  = ch - b * Dd;
    size_t base = (size_t)b * Ts * Dd + (size_t)c * CH * Dd + d;

    float P = 1.0f, hacc = 0.0f;
    #pragma unroll 1
    for (int t0 = 0; t0 < CH; t0 += 8) {
        float2 v[8];
        #pragma unroll
        for (int u = 0; u < 8; u++) v[u] = g_ax[base + (size_t)(t0 + u) * Dd];
        #pragma unroll
        for (int u = 0; u < 8; u++) {
            P *= v[u].x;
            hacc = fmaf(v[u].x, hacc, v[u].y);
        }
    }
    g_P[c * NCHAN + ch] = P;
    g_h[c * NCHAN + ch] = hacc;
}

// ---------------------------------------------------------------------------
// Kernel 2b: cross-chunk recurrence (32 steps per channel, L2-resident)
// ---------------------------------------------------------------------------
__global__ __launch_bounds__(128) void scan_link_kernel() {
    int ch = blockIdx.x * 128 + threadIdx.x;
    float H = 0.0f;
    #pragma unroll
    for (int c = 0; c < NCH; c++) {
        g_H[c * NCHAN + ch] = H;
        H = fmaf(g_P[c * NCHAN + ch], H, g_h[c * NCHAN + ch]);
    }
}

// ---------------------------------------------------------------------------
// Kernel 2c: seeded local scan, write output
// ---------------------------------------------------------------------------
__global__ __launch_bounds__(128) void scan_final_kernel(float* __restrict__ out) {
    int ch = blockIdx.x * 128 + threadIdx.x;
    int c  = blockIdx.y;
    int b  = ch / Dd;
    int d  = ch - b * Dd;
    size_t base = (size_t)b * Ts * Dd + (size_t)c * CH * Dd + d;

    float hacc = g_H[c * NCHAN + ch];
    #pragma unroll 1
    for (int t0 = 0; t0 < CH; t0 += 8) {
        float2 v[8];
        #pragma unroll
        for (int u = 0; u < 8; u++) v[u] = g_ax[base + (size_t)(t0 + u) * Dd];
        #pragma unroll
        for (int u = 0; u < 8; u++) {
            hacc = fmaf(v[u].x, hacc, v[u].y);
            out[base + (size_t)(t0 + u) * Dd] = hacc;
        }
    }
}

// ---------------------------------------------------------------------------
extern "C" void kernel_launch(void* const* d_in, const int* in_sizes, int n_in,
                              void* d_out, int out_size) {
    const float* act = (const float*)d_in[0];
    const int*   pos = (const int*)  d_in[1];
    const float* wig = (const float*)d_in[2];
    const float* big = (const float*)d_in[3];
    const float* wrg = (const float*)d_in[4];
    const float* brg = (const float*)d_in[5];
    const float* rp  = (const float*)d_in[6];
    float* out = (float*)d_out;

    static int smem_set = 0;
    if (!smem_set) {
        cudaFuncSetAttribute(gates_mma_kernel,
                             cudaFuncAttributeMaxDynamicSharedMemorySize, SMEM_B);
        smem_set = 1;
    }

    sp_kernel<<<(Dd + 255) / 256, 256>>>(rp);
    wt_kernel<<<(Hh * 512 * BW) / 256, 256>>>(wig, wrg);

    dim3 grid(Mrows / 128, 2, Hh);   // 2560 CTAs
    gates_mma_kernel<<<grid, 256, SMEM_B>>>(act, pos, big, brg);

    dim3 sgrid(NCHAN / 128, NCH);    // (80, 32)
    scan_part_kernel<<<sgrid, 128>>>();
    scan_link_kernel<<<NCHAN / 128, 128>>>();
    scan_final_kernel<<<sgrid, 128>>>(out);
}